// round 6
// baseline (speedup 1.0000x reference)
#include <cuda_runtime.h>

#define DH 128
#define N_NODES_MAX 50000
#define N_GRAPHS_MAX 64
#define NPB 64   // nodes per block in GEMM

// ---------------- scratch (device globals: allocation-free) ----------------
__device__ float g_bufA[N_NODES_MAX * DH];   // aggregation target (both layers)
__device__ float g_bufB[N_NODES_MAX * DH];   // h1 / h2 (GEMM output, both layers)
__device__ float g_deg[N_NODES_MAX];
__device__ float g_dis[N_NODES_MAX];         // deg^{-1/2}
__device__ float g_pooled[N_GRAPHS_MAX * DH];
__device__ float g_cnt[N_GRAPHS_MAX];

// vectorized global reduction (sm_90+): 4 floats per red op
__device__ __forceinline__ void red_add_v4(float4* addr, float4 v) {
    asm volatile("red.global.add.v4.f32 [%0], {%1, %2, %3, %4};"
                 :: "l"(addr), "f"(v.x), "f"(v.y), "f"(v.z), "f"(v.w)
                 : "memory");
}

// ---------------- zero kernels ----------------
__global__ void k_zero_aux(int nN) {
    int i = blockIdx.x * blockDim.x + threadIdx.x;
    if (i < nN) g_deg[i] = 0.f;
    if (i < N_GRAPHS_MAX * DH) g_pooled[i] = 0.f;
    if (i < N_GRAPHS_MAX) g_cnt[i] = 0.f;
}

__global__ void k_zero_bufA(int n4) {
    int i = blockIdx.x * blockDim.x + threadIdx.x;
    if (i < n4) reinterpret_cast<float4*>(g_bufA)[i] = make_float4(0.f, 0.f, 0.f, 0.f);
}

// ---------------- degree / norm ----------------
__global__ void k_deg(const int* __restrict__ dst, int nE) {
    int e = blockIdx.x * blockDim.x + threadIdx.x;
    if (e < nE) atomicAdd(&g_deg[dst[e]], 1.0f);
}

__global__ void k_dis(int nN) {
    int i = blockIdx.x * blockDim.x + threadIdx.x;
    if (i < nN) {
        float d = g_deg[i];
        g_dis[i] = (d > 0.f) ? rsqrtf(d) : 0.f;
    }
}

// ---------------- edge scatter: agg[dst] += feat[src] * norm(e) ----------------
// one warp per edge; lane l handles float4 chunk l (128 floats total)
__global__ void k_scatter(const float4* __restrict__ x_ext, int use_ext, int nE) {
    int idx = blockIdx.x * blockDim.x + threadIdx.x;
    int e = idx >> 5;
    if (e >= nE) return;
    int lane = idx & 31;

    // src/dst arrays are passed via g_edge pointers baked in launch args below
    // (we re-read them from constant params: see launch wrapper)
    extern __shared__ int dummy[]; // unused; keeps signature simple
    (void)dummy;
    // NOTE: src/dst provided through the pointer table trick below
    // -- replaced by the real implementation in k_scatter2
}

// real scatter (src/dst passed explicitly)
__global__ void k_scatter2(const int* __restrict__ src, const int* __restrict__ dst,
                           const float4* __restrict__ x_ext, int use_ext, int nE) {
    int idx = blockIdx.x * blockDim.x + threadIdx.x;
    int e = idx >> 5;
    if (e >= nE) return;
    int lane = idx & 31;

    const float4* feat = use_ext ? x_ext : reinterpret_cast<const float4*>(g_bufB);

    int s = __ldg(&src[e]);
    int d = __ldg(&dst[e]);
    float nm = __ldg(&g_dis[s]) * __ldg(&g_dis[d]);

    float4 v = feat[(size_t)s * 32 + lane];
    v.x *= nm; v.y *= nm; v.z *= nm; v.w *= nm;
    red_add_v4(reinterpret_cast<float4*>(g_bufA) + (size_t)d * 32 + lane, v);
}

// ---------------- GEMM + bias + ReLU:  bufB = relu(bufA @ W + b) ----------------
// 256 threads = 8 warps; each warp -> 8 nodes; lane -> 4 output cols.
// W processed in k-chunks of 32 to stay under 48KB static smem.
__global__ void __launch_bounds__(256, 2)
k_gemm_relu(const float* __restrict__ W, const float* __restrict__ b, int nN) {
    __shared__ float Wsh[32 * DH];     // 16 KB: rows k0..k0+31 of W
    __shared__ float Ash[NPB * 32];    //  8 KB: A[node, k0..k0+31]
    __shared__ float bsh[DH];

    const float* A = g_bufA;
    float* O = g_bufB;

    int tid = threadIdx.x;
    int node0 = blockIdx.x * NPB;
    if (tid < DH / 4)
        reinterpret_cast<float4*>(bsh)[tid] = reinterpret_cast<const float4*>(b)[tid];

    int warp = tid >> 5, lane = tid & 31;

    float acc[8][4];
#pragma unroll
    for (int nn = 0; nn < 8; nn++) {
        acc[nn][0] = 0.f; acc[nn][1] = 0.f; acc[nn][2] = 0.f; acc[nn][3] = 0.f;
    }

    for (int k0 = 0; k0 < DH; k0 += 32) {
        __syncthreads();
        // load W chunk: 32*128 floats = 1024 float4 / 256 threads
#pragma unroll
        for (int i = tid; i < 32 * DH / 4; i += 256)
            reinterpret_cast<float4*>(Wsh)[i] =
                reinterpret_cast<const float4*>(W + (size_t)k0 * DH)[i];
        // load A chunk: 64 nodes x 32 k = 512 float4
#pragma unroll
        for (int i = tid; i < NPB * 8; i += 256) {
            int n = node0 + (i >> 3);
            float4 av = make_float4(0.f, 0.f, 0.f, 0.f);
            if (n < nN)
                av = *reinterpret_cast<const float4*>(
                        &A[(size_t)n * DH + k0 + ((i & 7) << 2)]);
            reinterpret_cast<float4*>(Ash)[i] = av;
        }
        __syncthreads();

        const float* Ab = &Ash[(warp * 8) * 32];
#pragma unroll 8
        for (int kk = 0; kk < 32; kk++) {
            float4 w = reinterpret_cast<const float4*>(&Wsh[kk * DH])[lane];
#pragma unroll
            for (int nn = 0; nn < 8; nn++) {
                float a = Ab[nn * 32 + kk];
                acc[nn][0] = fmaf(a, w.x, acc[nn][0]);
                acc[nn][1] = fmaf(a, w.y, acc[nn][1]);
                acc[nn][2] = fmaf(a, w.z, acc[nn][2]);
                acc[nn][3] = fmaf(a, w.w, acc[nn][3]);
            }
        }
    }

    float4 bb = reinterpret_cast<const float4*>(bsh)[lane];
#pragma unroll
    for (int nn = 0; nn < 8; nn++) {
        int n = node0 + warp * 8 + nn;
        if (n < nN) {
            float4 o;
            o.x = fmaxf(acc[nn][0] + bb.x, 0.f);
            o.y = fmaxf(acc[nn][1] + bb.y, 0.f);
            o.z = fmaxf(acc[nn][2] + bb.z, 0.f);
            o.w = fmaxf(acc[nn][3] + bb.w, 0.f);
            reinterpret_cast<float4*>(O)[(size_t)n * 32 + lane] = o;
        }
    }
}

// ---------------- pooling: pooled[g] += h2[n]; cnt[g] += 1 ----------------
__global__ void k_pool(const int* __restrict__ gid, int nN) {
    int idx = blockIdx.x * blockDim.x + threadIdx.x;
    int n = idx >> 5;
    if (n >= nN) return;
    int lane = idx & 31;
    int g = __ldg(&gid[n]);
    float4 v = reinterpret_cast<const float4*>(g_bufB)[(size_t)n * 32 + lane];
    red_add_v4(reinterpret_cast<float4*>(&g_pooled[(size_t)g * DH]) + lane, v);
    if (lane == 0) atomicAdd(&g_cnt[g], 1.0f);
}

// ---------------- classifier: out[g][c] = (pooled[g]/cnt[g]) . Wc[:,c] + bc[c] ----
__global__ void k_logits(const float* __restrict__ Wc, const float* __restrict__ bc,
                         float* __restrict__ out, int nG) {
    int t = threadIdx.x;      // 512 threads
    int g = t >> 3, c = t & 7;
    if (g >= nG) return;
    float s = 0.f;
#pragma unroll 8
    for (int k = 0; k < DH; k++)
        s = fmaf(g_pooled[g * DH + k], __ldg(&Wc[k * 8 + c]), s);
    float cnt = fmaxf(g_cnt[g], 1.0f);
    out[g * 8 + c] = s / cnt + bc[c];
}

// ---------------- launch ----------------
extern "C" void kernel_launch(void* const* d_in, const int* in_sizes, int n_in,
                              void* d_out, int out_size) {
    const float* x  = (const float*)d_in[0];
    const int*   ei = (const int*)  d_in[1];
    const int*   gid= (const int*)  d_in[2];
    const float* W1 = (const float*)d_in[3];
    const float* b1 = (const float*)d_in[4];
    const float* W2 = (const float*)d_in[5];
    const float* b2 = (const float*)d_in[6];
    const float* Wc = (const float*)d_in[7];
    const float* bc = (const float*)d_in[8];
    float* out = (float*)d_out;

    int nN = in_sizes[0] / DH;
    int nE = in_sizes[1] / 2;
    int nG = out_size / 8;
    const int* src = ei;
    const int* dst = ei + nE;

    const int T = 256;
    int gN   = (nN + T - 1) / T;
    int gE   = (nE + T - 1) / T;
    int gE32 = (int)(((long long)nE * 32 + T - 1) / T);
    int gN32 = (int)(((long long)nN * 32 + T - 1) / T);
    int gBuf = (nN * 32 + T - 1) / T;           // float4 count of bufA
    int gGemm = (nN + NPB - 1) / NPB;

    // degree + norm + zero aux
    k_zero_aux<<<gN, T>>>(nN);
    k_deg<<<gE, T>>>(dst, nE);
    k_dis<<<gN, T>>>(nN);

    // layer 1
    k_zero_bufA<<<gBuf, T>>>(nN * 32);
    k_scatter2<<<gE32, T>>>(src, dst, (const float4*)x, 1, nE);
    k_gemm_relu<<<gGemm, T>>>(W1, b1, nN);

    // layer 2
    k_zero_bufA<<<gBuf, T>>>(nN * 32);
    k_scatter2<<<gE32, T>>>(src, dst, (const float4*)x, 0, nE);  // reads g_bufB
    k_gemm_relu<<<gGemm, T>>>(W2, b2, nN);

    // pool + classify
    k_pool<<<gN32, T>>>(gid, nN);
    k_logits<<<1, 512>>>(Wc, bc, out, nG);
}

// round 7
// speedup vs baseline: 1.3383x; 1.3383x over previous
#include <cuda_runtime.h>

#define DH 128
#define N_NODES_MAX 50000
#define N_EDGES_MAX 1600000
#define N_GRAPHS_MAX 64
#define NPB 64   // nodes per block in GEMM

// ---------------- scratch (device globals: allocation-free) ----------------
__device__ float g_bufA[N_NODES_MAX * DH];   // aggregation result (both layers)
__device__ float g_bufB[N_NODES_MAX * DH];   // h1 / h2 (GEMM output, both layers)
__device__ float g_dis[N_NODES_MAX];         // deg^{-1/2}
__device__ int   g_count[N_NODES_MAX];       // in-degree (int)
__device__ int   g_off[N_NODES_MAX + 1];     // CSR offsets (by dst)
__device__ int   g_cur[N_NODES_MAX];         // build cursors
__device__ int   g_srcs[N_EDGES_MAX];        // CSR: src node per edge slot
__device__ float g_pooled[N_GRAPHS_MAX * DH];
__device__ float g_cnt[N_GRAPHS_MAX];

// vectorized global reduction (sm_90+): 4 floats per red op (pooling only)
__device__ __forceinline__ void red_add_v4(float4* addr, float4 v) {
    asm volatile("red.global.add.v4.f32 [%0], {%1, %2, %3, %4};"
                 :: "l"(addr), "f"(v.x), "f"(v.y), "f"(v.z), "f"(v.w)
                 : "memory");
}

// ---------------- init: zero counters ----------------
__global__ void k_zero_aux(int nN) {
    int i = blockIdx.x * blockDim.x + threadIdx.x;
    if (i < nN) g_count[i] = 0;
    if (i < N_GRAPHS_MAX * DH) g_pooled[i] = 0.f;
    if (i < N_GRAPHS_MAX) g_cnt[i] = 0.f;
}

// ---------------- histogram of incoming degree ----------------
__global__ void k_hist(const int* __restrict__ dst, int nE) {
    int e = blockIdx.x * blockDim.x + threadIdx.x;
    if (e < nE) atomicAdd(&g_count[dst[e]], 1);
}

// ---------------- single-block exclusive scan + dis computation ----------------
__global__ void __launch_bounds__(1024, 1) k_scan(int nN) {
    __shared__ int sums[1024];
    int t = threadIdx.x;
    int C = (nN + 1023) >> 10;
    int lo = t * C;
    int hi = min(lo + C, nN);

    int s = 0;
    for (int i = lo; i < hi; i++) s += g_count[i];
    sums[t] = s;
    __syncthreads();

    // inclusive Hillis-Steele scan over 1024 partials
    for (int off = 1; off < 1024; off <<= 1) {
        int u = (t >= off) ? sums[t - off] : 0;
        __syncthreads();
        sums[t] += u;
        __syncthreads();
    }

    int run = sums[t] - s;   // exclusive base for this chunk
    for (int i = lo; i < hi; i++) {
        g_off[i] = run;
        g_cur[i] = run;
        int c = g_count[i];
        g_dis[i] = (c > 0) ? rsqrtf((float)c) : 0.f;
        run += c;
    }
    if (t == 1023) g_off[nN] = sums[1023];
}

// ---------------- CSR build: permute edges into dst-grouped order ----------------
__global__ void k_build(const int* __restrict__ src, const int* __restrict__ dst, int nE) {
    int e = blockIdx.x * blockDim.x + threadIdx.x;
    if (e >= nE) return;
    int d = dst[e];
    int pos = atomicAdd(&g_cur[d], 1);
    g_srcs[pos] = src[e];
}

// ---------------- gather: bufA[n] = dis[n] * sum_{s in in(n)} dis[s]*feat[s] ----
// one warp per node; lane handles one float4 chunk (128 floats/node); no atomics.
__global__ void __launch_bounds__(256) k_gather(const float4* __restrict__ x_ext,
                                                int use_ext, int nN) {
    int idx = blockIdx.x * blockDim.x + threadIdx.x;
    int n = idx >> 5;
    if (n >= nN) return;
    int lane = idx & 31;

    const float4* feat = use_ext ? x_ext : reinterpret_cast<const float4*>(g_bufB);

    int b = g_off[n], e = g_off[n + 1];
    float4 acc = make_float4(0.f, 0.f, 0.f, 0.f);

    int i = b;
    for (; i + 4 <= e; i += 4) {
        int s0 = g_srcs[i], s1 = g_srcs[i + 1], s2 = g_srcs[i + 2], s3 = g_srcs[i + 3];
        float d0 = g_dis[s0], d1 = g_dis[s1], d2 = g_dis[s2], d3 = g_dis[s3];
        float4 v0 = feat[(size_t)s0 * 32 + lane];
        float4 v1 = feat[(size_t)s1 * 32 + lane];
        float4 v2 = feat[(size_t)s2 * 32 + lane];
        float4 v3 = feat[(size_t)s3 * 32 + lane];
        acc.x = fmaf(d0, v0.x, fmaf(d1, v1.x, fmaf(d2, v2.x, fmaf(d3, v3.x, acc.x))));
        acc.y = fmaf(d0, v0.y, fmaf(d1, v1.y, fmaf(d2, v2.y, fmaf(d3, v3.y, acc.y))));
        acc.z = fmaf(d0, v0.z, fmaf(d1, v1.z, fmaf(d2, v2.z, fmaf(d3, v3.z, acc.z))));
        acc.w = fmaf(d0, v0.w, fmaf(d1, v1.w, fmaf(d2, v2.w, fmaf(d3, v3.w, acc.w))));
    }
    for (; i < e; i++) {
        int s = g_srcs[i];
        float ds = g_dis[s];
        float4 v = feat[(size_t)s * 32 + lane];
        acc.x = fmaf(ds, v.x, acc.x);
        acc.y = fmaf(ds, v.y, acc.y);
        acc.z = fmaf(ds, v.z, acc.z);
        acc.w = fmaf(ds, v.w, acc.w);
    }

    float dn = g_dis[n];
    acc.x *= dn; acc.y *= dn; acc.z *= dn; acc.w *= dn;
    reinterpret_cast<float4*>(g_bufA)[(size_t)n * 32 + lane] = acc;
}

// ---------------- GEMM + bias + ReLU:  bufB = relu(bufA @ W + b) ----------------
__global__ void __launch_bounds__(256, 2)
k_gemm_relu(const float* __restrict__ W, const float* __restrict__ b, int nN) {
    __shared__ float Wsh[32 * DH];     // 16 KB
    __shared__ float Ash[NPB * 32];    //  8 KB
    __shared__ float bsh[DH];

    const float* A = g_bufA;
    float* O = g_bufB;

    int tid = threadIdx.x;
    int node0 = blockIdx.x * NPB;
    if (tid < DH / 4)
        reinterpret_cast<float4*>(bsh)[tid] = reinterpret_cast<const float4*>(b)[tid];

    int warp = tid >> 5, lane = tid & 31;

    float acc[8][4];
#pragma unroll
    for (int nn = 0; nn < 8; nn++) {
        acc[nn][0] = 0.f; acc[nn][1] = 0.f; acc[nn][2] = 0.f; acc[nn][3] = 0.f;
    }

    for (int k0 = 0; k0 < DH; k0 += 32) {
        __syncthreads();
#pragma unroll
        for (int i = tid; i < 32 * DH / 4; i += 256)
            reinterpret_cast<float4*>(Wsh)[i] =
                reinterpret_cast<const float4*>(W + (size_t)k0 * DH)[i];
#pragma unroll
        for (int i = tid; i < NPB * 8; i += 256) {
            int n = node0 + (i >> 3);
            float4 av = make_float4(0.f, 0.f, 0.f, 0.f);
            if (n < nN)
                av = *reinterpret_cast<const float4*>(
                        &A[(size_t)n * DH + k0 + ((i & 7) << 2)]);
            reinterpret_cast<float4*>(Ash)[i] = av;
        }
        __syncthreads();

        const float* Ab = &Ash[(warp * 8) * 32];
#pragma unroll 8
        for (int kk = 0; kk < 32; kk++) {
            float4 w = reinterpret_cast<const float4*>(&Wsh[kk * DH])[lane];
#pragma unroll
            for (int nn = 0; nn < 8; nn++) {
                float a = Ab[nn * 32 + kk];
                acc[nn][0] = fmaf(a, w.x, acc[nn][0]);
                acc[nn][1] = fmaf(a, w.y, acc[nn][1]);
                acc[nn][2] = fmaf(a, w.z, acc[nn][2]);
                acc[nn][3] = fmaf(a, w.w, acc[nn][3]);
            }
        }
    }

    float4 bb = reinterpret_cast<const float4*>(bsh)[lane];
#pragma unroll
    for (int nn = 0; nn < 8; nn++) {
        int n = node0 + warp * 8 + nn;
        if (n < nN) {
            float4 o;
            o.x = fmaxf(acc[nn][0] + bb.x, 0.f);
            o.y = fmaxf(acc[nn][1] + bb.y, 0.f);
            o.z = fmaxf(acc[nn][2] + bb.z, 0.f);
            o.w = fmaxf(acc[nn][3] + bb.w, 0.f);
            reinterpret_cast<float4*>(O)[(size_t)n * 32 + lane] = o;
        }
    }
}

// ---------------- pooling: pooled[g] += h2[n]; cnt[g] += 1 ----------------
__global__ void k_pool(const int* __restrict__ gid, int nN) {
    int idx = blockIdx.x * blockDim.x + threadIdx.x;
    int n = idx >> 5;
    if (n >= nN) return;
    int lane = idx & 31;
    int g = __ldg(&gid[n]);
    float4 v = reinterpret_cast<const float4*>(g_bufB)[(size_t)n * 32 + lane];
    red_add_v4(reinterpret_cast<float4*>(&g_pooled[(size_t)g * DH]) + lane, v);
    if (lane == 0) atomicAdd(&g_cnt[g], 1.0f);
}

// ---------------- classifier ----------------
__global__ void k_logits(const float* __restrict__ Wc, const float* __restrict__ bc,
                         float* __restrict__ out, int nG) {
    int t = threadIdx.x;      // 512 threads
    int g = t >> 3, c = t & 7;
    if (g >= nG) return;
    float s = 0.f;
#pragma unroll 8
    for (int k = 0; k < DH; k++)
        s = fmaf(g_pooled[g * DH + k], __ldg(&Wc[k * 8 + c]), s);
    float cnt = fmaxf(g_cnt[g], 1.0f);
    out[g * 8 + c] = s / cnt + bc[c];
}

// ---------------- launch ----------------
extern "C" void kernel_launch(void* const* d_in, const int* in_sizes, int n_in,
                              void* d_out, int out_size) {
    const float* x  = (const float*)d_in[0];
    const int*   ei = (const int*)  d_in[1];
    const int*   gid= (const int*)  d_in[2];
    const float* W1 = (const float*)d_in[3];
    const float* b1 = (const float*)d_in[4];
    const float* W2 = (const float*)d_in[5];
    const float* b2 = (const float*)d_in[6];
    const float* Wc = (const float*)d_in[7];
    const float* bc = (const float*)d_in[8];
    float* out = (float*)d_out;

    int nN = in_sizes[0] / DH;
    int nE = in_sizes[1] / 2;
    int nG = out_size / 8;
    const int* src = ei;
    const int* dst = ei + nE;

    const int T = 256;
    int gN   = (nN + T - 1) / T;
    int gE   = (nE + T - 1) / T;
    int gN32 = (int)(((long long)nN * 32 + T - 1) / T);   // warp-per-node grids
    int gGemm = (nN + NPB - 1) / NPB;

    // CSR build (counting sort by dst) + degree norm
    k_zero_aux<<<gN, T>>>(nN);
    k_hist<<<gE, T>>>(dst, nE);
    k_scan<<<1, 1024>>>(nN);
    k_build<<<gE, T>>>(src, dst, nE);

    // layer 1: gather from x, GEMM
    k_gather<<<gN32, T>>>((const float4*)x, 1, nN);
    k_gemm_relu<<<gGemm, T>>>(W1, b1, nN);

    // layer 2: gather from h1 (g_bufB), GEMM
    k_gather<<<gN32, T>>>((const float4*)x, 0, nN);
    k_gemm_relu<<<gGemm, T>>>(W2, b2, nN);

    // pool + classify
    k_pool<<<gN32, T>>>(gid, nN);
    k_logits<<<1, 512>>>(Wc, bc, out, nG);
}

// round 8
// speedup vs baseline: 1.3896x; 1.0383x over previous
#include <cuda_runtime.h>
#include <cuda_bf16.h>

#define DH 128
#define N_NODES_MAX 50000
#define N_EDGES_MAX 1600000
#define N_GRAPHS_MAX 64
#define NPB 64   // nodes per block in GEMM

// ---------------- scratch (device globals: allocation-free) ----------------
__device__ float g_bufA[N_NODES_MAX * DH];           // aggregation result (fp32, GEMM input)
__device__ float g_bufB[N_NODES_MAX * DH];           // h2 (fp32, pooling input)
__device__ __nv_bfloat16 g_xb[N_NODES_MAX * DH];     // x * dis[n], bf16 (layer-1 gather src)
__device__ __nv_bfloat16 g_h1b[N_NODES_MAX * DH];    // h1 * dis[n], bf16 (layer-2 gather src)
__device__ float g_dis[N_NODES_MAX];                 // deg^{-1/2}
__device__ int   g_count[N_NODES_MAX];               // in-degree
__device__ int   g_off[N_NODES_MAX + 1];             // CSR offsets (by dst)
__device__ int   g_cur[N_NODES_MAX];                 // build cursors
__device__ int   g_srcs[N_EDGES_MAX];                // CSR: src node per slot
__device__ float g_pooled[N_GRAPHS_MAX * DH];
__device__ float g_cnt[N_GRAPHS_MAX];

__device__ __forceinline__ void red_add_v4(float4* addr, float4 v) {
    asm volatile("red.global.add.v4.f32 [%0], {%1, %2, %3, %4};"
                 :: "l"(addr), "f"(v.x), "f"(v.y), "f"(v.z), "f"(v.w)
                 : "memory");
}

// ---------------- init: zero counters ----------------
__global__ void k_zero_aux(int nN) {
    int i = blockIdx.x * blockDim.x + threadIdx.x;
    if (i < nN) g_count[i] = 0;
    if (i < N_GRAPHS_MAX * DH) g_pooled[i] = 0.f;
    if (i < N_GRAPHS_MAX) g_cnt[i] = 0.f;
}

// ---------------- histogram of incoming degree (2 edges/thread) ----------------
__global__ void k_hist(const int* __restrict__ dst, int nE) {
    int t = blockIdx.x * blockDim.x + threadIdx.x;
    int e0 = t * 2;
    if (e0 < nE)     atomicAdd(&g_count[dst[e0]], 1);
    if (e0 + 1 < nE) atomicAdd(&g_count[dst[e0 + 1]], 1);
}

// ---------------- single-block exclusive scan + dis ----------------
__global__ void __launch_bounds__(1024, 1) k_scan(int nN) {
    __shared__ int sums[1024];
    int t = threadIdx.x;
    int C = (nN + 1023) >> 10;
    int lo = t * C;
    int hi = min(lo + C, nN);

    int s = 0;
    for (int i = lo; i < hi; i++) s += g_count[i];
    sums[t] = s;
    __syncthreads();

    for (int off = 1; off < 1024; off <<= 1) {
        int u = (t >= off) ? sums[t - off] : 0;
        __syncthreads();
        sums[t] += u;
        __syncthreads();
    }

    int run = sums[t] - s;
    for (int i = lo; i < hi; i++) {
        g_off[i] = run;
        g_cur[i] = run;
        int c = g_count[i];
        g_dis[i] = (c > 0) ? rsqrtf((float)c) : 0.f;
        run += c;
    }
    if (t == 1023) g_off[nN] = sums[1023];
}

// ---------------- CSR build (2 edges/thread for MLP) ----------------
__global__ void k_build(const int* __restrict__ src, const int* __restrict__ dst, int nE) {
    int t = blockIdx.x * blockDim.x + threadIdx.x;
    int e0 = t * 2;
    if (e0 < nE) {
        int d = dst[e0];
        int pos = atomicAdd(&g_cur[d], 1);
        g_srcs[pos] = src[e0];
    }
    if (e0 + 1 < nE) {
        int d = dst[e0 + 1];
        int pos = atomicAdd(&g_cur[d], 1);
        g_srcs[pos] = src[e0 + 1];
    }
}

// ---------------- pre-scale x: xb[n] = bf16(x[n] * dis[n]) ----------------
__global__ void k_scale_x(const float4* __restrict__ x, int nN) {
    int idx = blockIdx.x * blockDim.x + threadIdx.x;
    int n = idx >> 5;
    if (n >= nN) return;
    int lane = idx & 31;
    float d = g_dis[n];
    float4 v = x[(size_t)n * 32 + lane];
    __nv_bfloat162 p0 = __float22bfloat162_rn(make_float2(v.x * d, v.y * d));
    __nv_bfloat162 p1 = __float22bfloat162_rn(make_float2(v.z * d, v.w * d));
    uint2 u;
    u.x = *reinterpret_cast<unsigned*>(&p0);
    u.y = *reinterpret_cast<unsigned*>(&p1);
    reinterpret_cast<uint2*>(g_xb)[(size_t)n * 32 + lane] = u;
}

// ---------------- gather: bufA[n] = dis[n] * sum_{s in in(n)} feat_pre[s] ------
// one warp per node; lane handles 4 values (one uint2 = 4 bf16) per edge.
// use_x: 1 -> read g_xb, 0 -> read g_h1b (selected in-kernel; device globals).
__global__ void __launch_bounds__(256) k_gather(int use_x, int nN) {
    int idx = blockIdx.x * blockDim.x + threadIdx.x;
    int n = idx >> 5;
    if (n >= nN) return;
    int lane = idx & 31;

    const uint2* feat = reinterpret_cast<const uint2*>(use_x ? g_xb : g_h1b);

    int b = g_off[n], e = g_off[n + 1];
    float4 acc = make_float4(0.f, 0.f, 0.f, 0.f);

    int i = b;
    for (; i + 4 <= e; i += 4) {
        int s0 = g_srcs[i], s1 = g_srcs[i + 1], s2 = g_srcs[i + 2], s3 = g_srcs[i + 3];
        uint2 u0 = feat[(size_t)s0 * 32 + lane];
        uint2 u1 = feat[(size_t)s1 * 32 + lane];
        uint2 u2 = feat[(size_t)s2 * 32 + lane];
        uint2 u3 = feat[(size_t)s3 * 32 + lane];
#pragma unroll
        for (int j = 0; j < 4; j++) {
            uint2 u = (j == 0) ? u0 : (j == 1) ? u1 : (j == 2) ? u2 : u3;
            float2 f0 = __bfloat1622float2(*reinterpret_cast<__nv_bfloat162*>(&u.x));
            float2 f1 = __bfloat1622float2(*reinterpret_cast<__nv_bfloat162*>(&u.y));
            acc.x += f0.x; acc.y += f0.y; acc.z += f1.x; acc.w += f1.y;
        }
    }
    for (; i < e; i++) {
        int s = g_srcs[i];
        uint2 u = feat[(size_t)s * 32 + lane];
        float2 f0 = __bfloat1622float2(*reinterpret_cast<__nv_bfloat162*>(&u.x));
        float2 f1 = __bfloat1622float2(*reinterpret_cast<__nv_bfloat162*>(&u.y));
        acc.x += f0.x; acc.y += f0.y; acc.z += f1.x; acc.w += f1.y;
    }

    float dn = g_dis[n];
    acc.x *= dn; acc.y *= dn; acc.z *= dn; acc.w *= dn;
    reinterpret_cast<float4*>(g_bufA)[(size_t)n * 32 + lane] = acc;
}

// ---------------- GEMM + bias + ReLU -------------------------------------
// mode 0: write bf16(relu(.)*dis[n]) to g_h1b   (layer 1)
// mode 1: write fp32 relu(.) to g_bufB          (layer 2)
__global__ void __launch_bounds__(256, 2)
k_gemm_relu(const float* __restrict__ W, const float* __restrict__ b, int nN, int mode) {
    __shared__ float Wsh[32 * DH];     // 16 KB
    __shared__ float Ash[NPB * 32];    //  8 KB
    __shared__ float bsh[DH];

    const float* A = g_bufA;

    int tid = threadIdx.x;
    int node0 = blockIdx.x * NPB;
    if (tid < DH / 4)
        reinterpret_cast<float4*>(bsh)[tid] = reinterpret_cast<const float4*>(b)[tid];

    int warp = tid >> 5, lane = tid & 31;

    float acc[8][4];
#pragma unroll
    for (int nn = 0; nn < 8; nn++) {
        acc[nn][0] = 0.f; acc[nn][1] = 0.f; acc[nn][2] = 0.f; acc[nn][3] = 0.f;
    }

    for (int k0 = 0; k0 < DH; k0 += 32) {
        __syncthreads();
#pragma unroll
        for (int i = tid; i < 32 * DH / 4; i += 256)
            reinterpret_cast<float4*>(Wsh)[i] =
                reinterpret_cast<const float4*>(W + (size_t)k0 * DH)[i];
#pragma unroll
        for (int i = tid; i < NPB * 8; i += 256) {
            int n = node0 + (i >> 3);
            float4 av = make_float4(0.f, 0.f, 0.f, 0.f);
            if (n < nN)
                av = *reinterpret_cast<const float4*>(
                        &A[(size_t)n * DH + k0 + ((i & 7) << 2)]);
            reinterpret_cast<float4*>(Ash)[i] = av;
        }
        __syncthreads();

        const float* Ab = &Ash[(warp * 8) * 32];
#pragma unroll 8
        for (int kk = 0; kk < 32; kk++) {
            float4 w = reinterpret_cast<const float4*>(&Wsh[kk * DH])[lane];
#pragma unroll
            for (int nn = 0; nn < 8; nn++) {
                float a = Ab[nn * 32 + kk];
                acc[nn][0] = fmaf(a, w.x, acc[nn][0]);
                acc[nn][1] = fmaf(a, w.y, acc[nn][1]);
                acc[nn][2] = fmaf(a, w.z, acc[nn][2]);
                acc[nn][3] = fmaf(a, w.w, acc[nn][3]);
            }
        }
    }

    float4 bb = reinterpret_cast<const float4*>(bsh)[lane];
#pragma unroll
    for (int nn = 0; nn < 8; nn++) {
        int n = node0 + warp * 8 + nn;
        if (n >= nN) continue;
        float4 o;
        o.x = fmaxf(acc[nn][0] + bb.x, 0.f);
        o.y = fmaxf(acc[nn][1] + bb.y, 0.f);
        o.z = fmaxf(acc[nn][2] + bb.z, 0.f);
        o.w = fmaxf(acc[nn][3] + bb.w, 0.f);
        if (mode == 0) {
            float d = g_dis[n];
            __nv_bfloat162 p0 = __float22bfloat162_rn(make_float2(o.x * d, o.y * d));
            __nv_bfloat162 p1 = __float22bfloat162_rn(make_float2(o.z * d, o.w * d));
            uint2 u;
            u.x = *reinterpret_cast<unsigned*>(&p0);
            u.y = *reinterpret_cast<unsigned*>(&p1);
            reinterpret_cast<uint2*>(g_h1b)[(size_t)n * 32 + lane] = u;
        } else {
            reinterpret_cast<float4*>(g_bufB)[(size_t)n * 32 + lane] = o;
        }
    }
}

// ---------------- pooling ----------------
__global__ void k_pool(const int* __restrict__ gid, int nN) {
    int idx = blockIdx.x * blockDim.x + threadIdx.x;
    int n = idx >> 5;
    if (n >= nN) return;
    int lane = idx & 31;
    int g = __ldg(&gid[n]);
    float4 v = reinterpret_cast<const float4*>(g_bufB)[(size_t)n * 32 + lane];
    red_add_v4(reinterpret_cast<float4*>(&g_pooled[(size_t)g * DH]) + lane, v);
    if (lane == 0) atomicAdd(&g_cnt[g], 1.0f);
}

// ---------------- classifier ----------------
__global__ void k_logits(const float* __restrict__ Wc, const float* __restrict__ bc,
                         float* __restrict__ out, int nG) {
    int t = threadIdx.x;      // 512 threads
    int g = t >> 3, c = t & 7;
    if (g >= nG) return;
    float s = 0.f;
#pragma unroll 8
    for (int k = 0; k < DH; k++)
        s = fmaf(g_pooled[g * DH + k], __ldg(&Wc[k * 8 + c]), s);
    float cnt = fmaxf(g_cnt[g], 1.0f);
    out[g * 8 + c] = s / cnt + bc[c];
}

// ---------------- launch ----------------
extern "C" void kernel_launch(void* const* d_in, const int* in_sizes, int n_in,
                              void* d_out, int out_size) {
    const float* x  = (const float*)d_in[0];
    const int*   ei = (const int*)  d_in[1];
    const int*   gid= (const int*)  d_in[2];
    const float* W1 = (const float*)d_in[3];
    const float* b1 = (const float*)d_in[4];
    const float* W2 = (const float*)d_in[5];
    const float* b2 = (const float*)d_in[6];
    const float* Wc = (const float*)d_in[7];
    const float* bc = (const float*)d_in[8];
    float* out = (float*)d_out;

    int nN = in_sizes[0] / DH;
    int nE = in_sizes[1] / 2;
    int nG = out_size / 8;
    const int* src = ei;
    const int* dst = ei + nE;

    const int T = 256;
    int gN   = (nN + T - 1) / T;
    int gE2  = (nE / 2 + T) / T;                          // 2 edges/thread grids
    int gN32 = (int)(((long long)nN * 32 + T - 1) / T);   // warp-per-node grids
    int gGemm = (nN + NPB - 1) / NPB;

    // CSR build (counting sort by dst) + degree norm
    k_zero_aux<<<gN, T>>>(nN);
    k_hist<<<gE2, T>>>(dst, nE);
    k_scan<<<1, 1024>>>(nN);
    k_build<<<gE2, T>>>(src, dst, nE);

    // pre-scale x into bf16
    k_scale_x<<<gN32, T>>>((const float4*)x, nN);

    // layer 1: gather from xb, GEMM -> h1b (bf16, pre-scaled)
    k_gather<<<gN32, T>>>(1, nN);
    k_gemm_relu<<<gGemm, T>>>(W1, b1, nN, 0);

    // layer 2: gather from h1b, GEMM -> bufB (fp32)
    k_gather<<<gN32, T>>>(0, nN);
    k_gemm_relu<<<gGemm, T>>>(W2, b2, nN, 1);

    // pool + classify
    k_pool<<<gN32, T>>>(gid, nN);
    k_logits<<<1, 512>>>(Wc, bc, out, nG);
}

// round 9
// speedup vs baseline: 1.5397x; 1.1080x over previous
#include <cuda_runtime.h>
#include <cuda_bf16.h>

#define DH 128
#define N_NODES_MAX 50000
#define N_EDGES_MAX 1600000
#define N_GRAPHS_MAX 64
#define NPB 64   // nodes per block in GEMM

// ---------------- scratch (device globals: allocation-free) ----------------
__device__ float g_bufA[N_NODES_MAX * DH];           // aggregation result (fp32, GEMM input)
__device__ __nv_bfloat16 g_xb[N_NODES_MAX * DH];     // x * dis[n], bf16 (layer-1 gather src)
__device__ __nv_bfloat16 g_h1b[N_NODES_MAX * DH];    // h1 * dis[n], bf16 (layer-2 gather src)
__device__ float g_dis[N_NODES_MAX];                 // deg^{-1/2}
__device__ int   g_count[N_NODES_MAX];               // in-degree
__device__ int   g_off[N_NODES_MAX + 1];             // CSR offsets (by dst)
__device__ int   g_cur[N_NODES_MAX];                 // build cursors
__device__ int   g_srcs[N_EDGES_MAX];                // CSR: src node per slot
__device__ float g_pooled[N_GRAPHS_MAX * DH];
__device__ float g_cnt[N_GRAPHS_MAX];

__device__ __forceinline__ void red_add_v4(float4* addr, float4 v) {
    asm volatile("red.global.add.v4.f32 [%0], {%1, %2, %3, %4};"
                 :: "l"(addr), "f"(v.x), "f"(v.y), "f"(v.z), "f"(v.w)
                 : "memory");
}

// ---------------- init: zero counters ----------------
__global__ void k_zero_aux(int nN) {
    int i = blockIdx.x * blockDim.x + threadIdx.x;
    if (i < nN) g_count[i] = 0;
    if (i < N_GRAPHS_MAX * DH) g_pooled[i] = 0.f;
    if (i < N_GRAPHS_MAX) g_cnt[i] = 0.f;
}

// ---------------- histogram of incoming degree (4 edges/thread) ----------------
__global__ void k_hist(const int* __restrict__ dst, int nE) {
    int t = blockIdx.x * blockDim.x + threadIdx.x;
    int e0 = t * 4;
#pragma unroll
    for (int j = 0; j < 4; j++)
        if (e0 + j < nE) atomicAdd(&g_count[dst[e0 + j]], 1);
}

// ---------------- single-block exclusive scan + dis ----------------
__global__ void __launch_bounds__(1024, 1) k_scan(int nN) {
    __shared__ int sums[1024];
    int t = threadIdx.x;
    int C = (nN + 1023) >> 10;
    int lo = t * C;
    int hi = min(lo + C, nN);

    int s = 0;
    for (int i = lo; i < hi; i++) s += g_count[i];
    sums[t] = s;
    __syncthreads();

    for (int off = 1; off < 1024; off <<= 1) {
        int u = (t >= off) ? sums[t - off] : 0;
        __syncthreads();
        sums[t] += u;
        __syncthreads();
    }

    int run = sums[t] - s;
    for (int i = lo; i < hi; i++) {
        g_off[i] = run;
        g_cur[i] = run;
        int c = g_count[i];
        g_dis[i] = (c > 0) ? rsqrtf((float)c) : 0.f;
        run += c;
    }
    if (t == 1023) g_off[nN] = sums[1023];
}

// ---------------- CSR build (4 edges/thread for MLP) ----------------
__global__ void k_build(const int* __restrict__ src, const int* __restrict__ dst, int nE) {
    int t = blockIdx.x * blockDim.x + threadIdx.x;
    int e0 = t * 4;
    if (e0 + 4 <= nE) {
        int d0 = dst[e0], d1 = dst[e0+1], d2 = dst[e0+2], d3 = dst[e0+3];
        int s0 = src[e0], s1 = src[e0+1], s2 = src[e0+2], s3 = src[e0+3];
        int p0 = atomicAdd(&g_cur[d0], 1);
        int p1 = atomicAdd(&g_cur[d1], 1);
        int p2 = atomicAdd(&g_cur[d2], 1);
        int p3 = atomicAdd(&g_cur[d3], 1);
        g_srcs[p0] = s0; g_srcs[p1] = s1; g_srcs[p2] = s2; g_srcs[p3] = s3;
    } else {
        for (int j = 0; j < 4 && e0 + j < nE; j++) {
            int d = dst[e0 + j];
            int pos = atomicAdd(&g_cur[d], 1);
            g_srcs[pos] = src[e0 + j];
        }
    }
}

// ---------------- pre-scale x: xb[n] = bf16(x[n] * dis[n]) ----------------
__global__ void k_scale_x(const float4* __restrict__ x, int nN) {
    int idx = blockIdx.x * blockDim.x + threadIdx.x;
    int n = idx >> 5;
    if (n >= nN) return;
    int lane = idx & 31;
    float d = g_dis[n];
    float4 v = x[(size_t)n * 32 + lane];
    __nv_bfloat162 p0 = __float22bfloat162_rn(make_float2(v.x * d, v.y * d));
    __nv_bfloat162 p1 = __float22bfloat162_rn(make_float2(v.z * d, v.w * d));
    uint2 u;
    u.x = *reinterpret_cast<unsigned*>(&p0);
    u.y = *reinterpret_cast<unsigned*>(&p1);
    reinterpret_cast<uint2*>(g_xb)[(size_t)n * 32 + lane] = u;
}

// ---------------- gather: bufA[n] = dis[n] * sum_{s in in(n)} feat_pre[s] ------
// 2 nodes per warp: 16 lanes per node, each lane one uint4 (8 bf16) per edge.
__device__ __forceinline__ void acc8(float* acc, uint4 u) {
    float2 f;
    f = __bfloat1622float2(*reinterpret_cast<__nv_bfloat162*>(&u.x));
    acc[0] += f.x; acc[1] += f.y;
    f = __bfloat1622float2(*reinterpret_cast<__nv_bfloat162*>(&u.y));
    acc[2] += f.x; acc[3] += f.y;
    f = __bfloat1622float2(*reinterpret_cast<__nv_bfloat162*>(&u.z));
    acc[4] += f.x; acc[5] += f.y;
    f = __bfloat1622float2(*reinterpret_cast<__nv_bfloat162*>(&u.w));
    acc[6] += f.x; acc[7] += f.y;
}

__global__ void __launch_bounds__(256) k_gather(int use_x, int nN) {
    int idx = blockIdx.x * blockDim.x + threadIdx.x;
    int n = idx >> 4;                 // one node per 16-lane group
    if (n >= nN) return;
    int lane = idx & 15;

    const uint4* feat = reinterpret_cast<const uint4*>(use_x ? g_xb : g_h1b);

    int b = g_off[n], e = g_off[n + 1];
    float acc[8] = {0.f, 0.f, 0.f, 0.f, 0.f, 0.f, 0.f, 0.f};

    int i = b;
    for (; i + 4 <= e; i += 4) {
        int s0 = __ldg(&g_srcs[i]);
        int s1 = __ldg(&g_srcs[i + 1]);
        int s2 = __ldg(&g_srcs[i + 2]);
        int s3 = __ldg(&g_srcs[i + 3]);
        uint4 u0 = __ldg(&feat[(size_t)s0 * 16 + lane]);
        uint4 u1 = __ldg(&feat[(size_t)s1 * 16 + lane]);
        uint4 u2 = __ldg(&feat[(size_t)s2 * 16 + lane]);
        uint4 u3 = __ldg(&feat[(size_t)s3 * 16 + lane]);
        acc8(acc, u0); acc8(acc, u1); acc8(acc, u2); acc8(acc, u3);
    }
    for (; i < e; i++) {
        int s = __ldg(&g_srcs[i]);
        uint4 u = __ldg(&feat[(size_t)s * 16 + lane]);
        acc8(acc, u);
    }

    float dn = g_dis[n];
#pragma unroll
    for (int j = 0; j < 8; j++) acc[j] *= dn;

    float4* orow = reinterpret_cast<float4*>(&g_bufA[(size_t)n * DH + lane * 8]);
    orow[0] = make_float4(acc[0], acc[1], acc[2], acc[3]);
    orow[1] = make_float4(acc[4], acc[5], acc[6], acc[7]);
}

// ---------------- GEMM + bias + ReLU -------------------------------------
// mode 0: write bf16(relu(.)*dis[n]) to g_h1b                 (layer 1)
// mode 1: fused pooling — red_add relu(.) into g_pooled[gid]  (layer 2)
__global__ void __launch_bounds__(256, 2)
k_gemm_relu(const float* __restrict__ W, const float* __restrict__ b,
            const int* __restrict__ gid, int nN, int mode) {
    __shared__ float Wsh[32 * DH];     // 16 KB
    __shared__ float Ash[NPB * 32];    //  8 KB
    __shared__ float bsh[DH];

    const float* A = g_bufA;

    int tid = threadIdx.x;
    int node0 = blockIdx.x * NPB;
    if (tid < DH / 4)
        reinterpret_cast<float4*>(bsh)[tid] = reinterpret_cast<const float4*>(b)[tid];

    int warp = tid >> 5, lane = tid & 31;

    float acc[8][4];
#pragma unroll
    for (int nn = 0; nn < 8; nn++) {
        acc[nn][0] = 0.f; acc[nn][1] = 0.f; acc[nn][2] = 0.f; acc[nn][3] = 0.f;
    }

    for (int k0 = 0; k0 < DH; k0 += 32) {
        __syncthreads();
#pragma unroll
        for (int i = tid; i < 32 * DH / 4; i += 256)
            reinterpret_cast<float4*>(Wsh)[i] =
                reinterpret_cast<const float4*>(W + (size_t)k0 * DH)[i];
#pragma unroll
        for (int i = tid; i < NPB * 8; i += 256) {
            int n = node0 + (i >> 3);
            float4 av = make_float4(0.f, 0.f, 0.f, 0.f);
            if (n < nN)
                av = *reinterpret_cast<const float4*>(
                        &A[(size_t)n * DH + k0 + ((i & 7) << 2)]);
            reinterpret_cast<float4*>(Ash)[i] = av;
        }
        __syncthreads();

        const float* Ab = &Ash[(warp * 8) * 32];
#pragma unroll 8
        for (int kk = 0; kk < 32; kk++) {
            float4 w = reinterpret_cast<const float4*>(&Wsh[kk * DH])[lane];
#pragma unroll
            for (int nn = 0; nn < 8; nn++) {
                float a = Ab[nn * 32 + kk];
                acc[nn][0] = fmaf(a, w.x, acc[nn][0]);
                acc[nn][1] = fmaf(a, w.y, acc[nn][1]);
                acc[nn][2] = fmaf(a, w.z, acc[nn][2]);
                acc[nn][3] = fmaf(a, w.w, acc[nn][3]);
            }
        }
    }

    float4 bb = reinterpret_cast<const float4*>(bsh)[lane];
#pragma unroll
    for (int nn = 0; nn < 8; nn++) {
        int n = node0 + warp * 8 + nn;
        if (n >= nN) continue;
        float4 o;
        o.x = fmaxf(acc[nn][0] + bb.x, 0.f);
        o.y = fmaxf(acc[nn][1] + bb.y, 0.f);
        o.z = fmaxf(acc[nn][2] + bb.z, 0.f);
        o.w = fmaxf(acc[nn][3] + bb.w, 0.f);
        if (mode == 0) {
            float d = g_dis[n];
            __nv_bfloat162 p0 = __float22bfloat162_rn(make_float2(o.x * d, o.y * d));
            __nv_bfloat162 p1 = __float22bfloat162_rn(make_float2(o.z * d, o.w * d));
            uint2 u;
            u.x = *reinterpret_cast<unsigned*>(&p0);
            u.y = *reinterpret_cast<unsigned*>(&p1);
            reinterpret_cast<uint2*>(g_h1b)[(size_t)n * 32 + lane] = u;
        } else {
            int g = __ldg(&gid[n]);
            red_add_v4(reinterpret_cast<float4*>(&g_pooled[(size_t)g * DH]) + lane, o);
            if (lane == 0) atomicAdd(&g_cnt[g], 1.0f);
        }
    }
}

// ---------------- classifier ----------------
__global__ void k_logits(const float* __restrict__ Wc, const float* __restrict__ bc,
                         float* __restrict__ out, int nG) {
    int t = threadIdx.x;      // 512 threads
    int g = t >> 3, c = t & 7;
    if (g >= nG) return;
    float s = 0.f;
#pragma unroll 8
    for (int k = 0; k < DH; k++)
        s = fmaf(g_pooled[g * DH + k], __ldg(&Wc[k * 8 + c]), s);
    float cnt = fmaxf(g_cnt[g], 1.0f);
    out[g * 8 + c] = s / cnt + bc[c];
}

// ---------------- launch ----------------
extern "C" void kernel_launch(void* const* d_in, const int* in_sizes, int n_in,
                              void* d_out, int out_size) {
    const float* x  = (const float*)d_in[0];
    const int*   ei = (const int*)  d_in[1];
    const int*   gid= (const int*)  d_in[2];
    const float* W1 = (const float*)d_in[3];
    const float* b1 = (const float*)d_in[4];
    const float* W2 = (const float*)d_in[5];
    const float* b2 = (const float*)d_in[6];
    const float* Wc = (const float*)d_in[7];
    const float* bc = (const float*)d_in[8];
    float* out = (float*)d_out;

    int nN = in_sizes[0] / DH;
    int nE = in_sizes[1] / 2;
    int nG = out_size / 8;
    const int* src = ei;
    const int* dst = ei + nE;

    const int T = 256;
    int gN   = (nN + T - 1) / T;
    int gE4  = (nE / 4 + T) / T;                          // 4 edges/thread grids
    int gN16 = (int)(((long long)nN * 16 + T - 1) / T);   // 16 lanes per node
    int gN32 = (int)(((long long)nN * 32 + T - 1) / T);   // 32 lanes per node
    int gGemm = (nN + NPB - 1) / NPB;

    // CSR build (counting sort by dst) + degree norm
    k_zero_aux<<<gN, T>>>(nN);
    k_hist<<<gE4, T>>>(dst, nE);
    k_scan<<<1, 1024>>>(nN);
    k_build<<<gE4, T>>>(src, dst, nE);

    // pre-scale x into bf16
    k_scale_x<<<gN32, T>>>((const float4*)x, nN);

    // layer 1: gather from xb, GEMM -> h1b (bf16, pre-scaled)
    k_gather<<<gN16, T>>>(1, nN);
    k_gemm_relu<<<gGemm, T>>>(W1, b1, gid, nN, 0);

    // layer 2: gather from h1b, GEMM (+fused pooling)
    k_gather<<<gN16, T>>>(0, nN);
    k_gemm_relu<<<gGemm, T>>>(W2, b2, gid, nN, 1);

    // classify
    k_logits<<<1, 512>>>(Wc, bc, out, nG);
}

// round 10
// speedup vs baseline: 1.5634x; 1.0154x over previous
#include <cuda_runtime.h>
#include <cuda_bf16.h>

#define DH 128
#define N_NODES_MAX 50000
#define N_EDGES_MAX 1600000
#define N_GRAPHS_MAX 64
#define NPB 64       // nodes per block in GEMM
#define AST 66       // Ash transposed stride (8B-aligned, low-conflict)

// ---------------- scratch (device globals: allocation-free) ----------------
__device__ float g_bufA[N_NODES_MAX * DH];           // aggregation result (fp32, GEMM input)
__device__ __nv_bfloat16 g_xb[N_NODES_MAX * DH];     // x * dis[n], bf16 (layer-1 gather src)
__device__ __nv_bfloat16 g_h1b[N_NODES_MAX * DH];    // h1 * dis[n], bf16 (layer-2 gather src)
__device__ float g_dis[N_NODES_MAX];                 // deg^{-1/2}
__device__ int   g_count[N_NODES_MAX];               // in-degree
__device__ int   g_off[N_NODES_MAX + 1];             // CSR offsets (by dst)
__device__ int   g_cur[N_NODES_MAX];                 // build cursors
__device__ int   g_srcs[N_EDGES_MAX];                // CSR: src node per slot
__device__ float g_pooled[N_GRAPHS_MAX * DH];
__device__ float g_cnt[N_GRAPHS_MAX];

__device__ __forceinline__ void red_add_v4(float4* addr, float4 v) {
    asm volatile("red.global.add.v4.f32 [%0], {%1, %2, %3, %4};"
                 :: "l"(addr), "f"(v.x), "f"(v.y), "f"(v.z), "f"(v.w)
                 : "memory");
}

// f32x2 packed helpers (Blackwell FFMA2 path — PTX-only)
__device__ __forceinline__ unsigned long long pk2(float x, float y) {
    unsigned long long u;
    asm("mov.b64 %0, {%1, %2};" : "=l"(u) : "f"(x), "f"(y));
    return u;
}
__device__ __forceinline__ void upk2(float& x, float& y, unsigned long long u) {
    asm("mov.b64 {%0, %1}, %2;" : "=f"(x), "=f"(y) : "l"(u));
}
__device__ __forceinline__ unsigned long long fma2(unsigned long long a,
                                                   unsigned long long b,
                                                   unsigned long long c) {
    unsigned long long d;
    asm("fma.rn.f32x2 %0, %1, %2, %3;" : "=l"(d) : "l"(a), "l"(b), "l"(c));
    return d;
}

// ---------------- init: zero in-degree counters ----------------
__global__ void k_zero_aux(int nN) {
    int i = blockIdx.x * blockDim.x + threadIdx.x;
    if (i < nN) g_count[i] = 0;
}

// ---------------- histogram (int4 vectorized, 4 edges/thread) ----------------
__global__ void k_hist4(const int4* __restrict__ dst4, int nQ) {
    int t = blockIdx.x * blockDim.x + threadIdx.x;
    if (t >= nQ) return;
    int4 d = __ldg(&dst4[t]);
    atomicAdd(&g_count[d.x], 1);
    atomicAdd(&g_count[d.y], 1);
    atomicAdd(&g_count[d.z], 1);
    atomicAdd(&g_count[d.w], 1);
}
__global__ void k_hist_tail(const int* __restrict__ dst, int e0, int nE) {
    int e = e0 + threadIdx.x;
    if (e < nE) atomicAdd(&g_count[dst[e]], 1);
}
__global__ void k_hist_s(const int* __restrict__ dst, int nE) {   // scalar fallback
    int t = blockIdx.x * blockDim.x + threadIdx.x;
    int e0 = t * 4;
#pragma unroll
    for (int j = 0; j < 4; j++)
        if (e0 + j < nE) atomicAdd(&g_count[dst[e0 + j]], 1);
}

// ---------------- single-block exclusive scan + dis ----------------
__global__ void __launch_bounds__(1024, 1) k_scan(int nN) {
    __shared__ int sums[1024];
    int t = threadIdx.x;
    int C = (nN + 1023) >> 10;
    int lo = t * C;
    int hi = min(lo + C, nN);

    int s = 0;
    for (int i = lo; i < hi; i++) s += g_count[i];
    sums[t] = s;
    __syncthreads();

    for (int off = 1; off < 1024; off <<= 1) {
        int u = (t >= off) ? sums[t - off] : 0;
        __syncthreads();
        sums[t] += u;
        __syncthreads();
    }

    int run = sums[t] - s;
    for (int i = lo; i < hi; i++) {
        g_off[i] = run;
        g_cur[i] = run;
        int c = g_count[i];
        g_dis[i] = (c > 0) ? rsqrtf((float)c) : 0.f;
        run += c;
    }
    if (t == 1023) g_off[nN] = sums[1023];
}

// ---------------- CSR build (int4 vectorized) ----------------
__global__ void k_build4(const int4* __restrict__ src4, const int4* __restrict__ dst4, int nQ) {
    int t = blockIdx.x * blockDim.x + threadIdx.x;
    if (t >= nQ) return;
    int4 d = __ldg(&dst4[t]);
    int4 s = __ldg(&src4[t]);
    int p0 = atomicAdd(&g_cur[d.x], 1);
    int p1 = atomicAdd(&g_cur[d.y], 1);
    int p2 = atomicAdd(&g_cur[d.z], 1);
    int p3 = atomicAdd(&g_cur[d.w], 1);
    g_srcs[p0] = s.x; g_srcs[p1] = s.y; g_srcs[p2] = s.z; g_srcs[p3] = s.w;
}
__global__ void k_build_tail(const int* __restrict__ src, const int* __restrict__ dst,
                             int e0, int nE) {
    int e = e0 + threadIdx.x;
    if (e < nE) {
        int pos = atomicAdd(&g_cur[dst[e]], 1);
        g_srcs[pos] = src[e];
    }
}
__global__ void k_build_s(const int* __restrict__ src, const int* __restrict__ dst, int nE) {
    int t = blockIdx.x * blockDim.x + threadIdx.x;
    int e0 = t * 4;
    for (int j = 0; j < 4 && e0 + j < nE; j++) {
        int pos = atomicAdd(&g_cur[dst[e0 + j]], 1);
        g_srcs[pos] = src[e0 + j];
    }
}

// -------- pre-scale x: xb[n] = bf16(x[n]*dis[n]); also zero pooled/cnt --------
__global__ void k_scale_x(const float4* __restrict__ x, int nN) {
    int idx = blockIdx.x * blockDim.x + threadIdx.x;
    if (idx < N_GRAPHS_MAX * DH) g_pooled[idx] = 0.f;
    if (idx < N_GRAPHS_MAX) g_cnt[idx] = 0.f;
    int n = idx >> 5;
    if (n >= nN) return;
    int lane = idx & 31;
    float d = g_dis[n];
    float4 v = x[(size_t)n * 32 + lane];
    __nv_bfloat162 p0 = __float22bfloat162_rn(make_float2(v.x * d, v.y * d));
    __nv_bfloat162 p1 = __float22bfloat162_rn(make_float2(v.z * d, v.w * d));
    uint2 u;
    u.x = *reinterpret_cast<unsigned*>(&p0);
    u.y = *reinterpret_cast<unsigned*>(&p1);
    reinterpret_cast<uint2*>(g_xb)[(size_t)n * 32 + lane] = u;
}

// ---------------- gather: bufA[n] = dis[n] * sum_{s in in(n)} feat_pre[s] ------
// 2 nodes per warp: 16 lanes per node, one uint4 (8 bf16) per lane per edge.
__device__ __forceinline__ void acc8(float* acc, uint4 u) {
    float2 f;
    f = __bfloat1622float2(*reinterpret_cast<__nv_bfloat162*>(&u.x));
    acc[0] += f.x; acc[1] += f.y;
    f = __bfloat1622float2(*reinterpret_cast<__nv_bfloat162*>(&u.y));
    acc[2] += f.x; acc[3] += f.y;
    f = __bfloat1622float2(*reinterpret_cast<__nv_bfloat162*>(&u.z));
    acc[4] += f.x; acc[5] += f.y;
    f = __bfloat1622float2(*reinterpret_cast<__nv_bfloat162*>(&u.w));
    acc[6] += f.x; acc[7] += f.y;
}

__global__ void __launch_bounds__(256) k_gather(int use_x, int nN) {
    int idx = blockIdx.x * blockDim.x + threadIdx.x;
    int n = idx >> 4;
    if (n >= nN) return;
    int lane = idx & 15;

    const uint4* feat = reinterpret_cast<const uint4*>(use_x ? g_xb : g_h1b);

    int b = g_off[n], e = g_off[n + 1];
    float acc[8] = {0.f, 0.f, 0.f, 0.f, 0.f, 0.f, 0.f, 0.f};

    int i = b;
    // 8-deep unroll: 8 feature LDG.128 in flight per lane
    for (; i + 8 <= e; i += 8) {
        int s[8];
#pragma unroll
        for (int j = 0; j < 8; j++) s[j] = __ldg(&g_srcs[i + j]);
        uint4 u[8];
#pragma unroll
        for (int j = 0; j < 8; j++) u[j] = __ldg(&feat[(size_t)s[j] * 16 + lane]);
#pragma unroll
        for (int j = 0; j < 8; j++) acc8(acc, u[j]);
    }
    for (; i + 4 <= e; i += 4) {
        int s0 = __ldg(&g_srcs[i]),     s1 = __ldg(&g_srcs[i + 1]);
        int s2 = __ldg(&g_srcs[i + 2]), s3 = __ldg(&g_srcs[i + 3]);
        uint4 u0 = __ldg(&feat[(size_t)s0 * 16 + lane]);
        uint4 u1 = __ldg(&feat[(size_t)s1 * 16 + lane]);
        uint4 u2 = __ldg(&feat[(size_t)s2 * 16 + lane]);
        uint4 u3 = __ldg(&feat[(size_t)s3 * 16 + lane]);
        acc8(acc, u0); acc8(acc, u1); acc8(acc, u2); acc8(acc, u3);
    }
    for (; i < e; i++) {
        int s = __ldg(&g_srcs[i]);
        uint4 u = __ldg(&feat[(size_t)s * 16 + lane]);
        acc8(acc, u);
    }

    float dn = g_dis[n];
#pragma unroll
    for (int j = 0; j < 8; j++) acc[j] *= dn;

    float4* orow = reinterpret_cast<float4*>(&g_bufA[(size_t)n * DH + lane * 8]);
    orow[0] = make_float4(acc[0], acc[1], acc[2], acc[3]);
    orow[1] = make_float4(acc[4], acc[5], acc[6], acc[7]);
}

// ---------------- GEMM + bias + ReLU (FFMA2 packed along node pairs) ----------
// Per warp: 8 nodes = 4 node-pairs; lane owns cols [lane*4, lane*4+4).
// accP[p][c] is f32x2 = (acc for node 2p, acc for node 2p+1) at col lane*4+c.
// mode 0: write bf16(relu(.)*dis[n]) to g_h1b                 (layer 1)
// mode 1: fused pooling — red_add relu(.) into g_pooled[gid]  (layer 2)
__global__ void __launch_bounds__(256, 2)
k_gemm_relu(const float* __restrict__ W, const float* __restrict__ b,
            const int* __restrict__ gid, int nN, int mode) {
    __shared__ float Wsh[32 * DH];       // 16 KB: W rows k0..k0+31
    __shared__ float Ash[32 * AST];      // 8.25 KB: A chunk TRANSPOSED [kk][node]
    __shared__ float bsh[DH];

    const float* A = g_bufA;

    int tid = threadIdx.x;
    int node0 = blockIdx.x * NPB;
    if (tid < DH / 4)
        reinterpret_cast<float4*>(bsh)[tid] = reinterpret_cast<const float4*>(b)[tid];

    int warp = tid >> 5, lane = tid & 31;

    unsigned long long accP[4][4];
#pragma unroll
    for (int p = 0; p < 4; p++)
#pragma unroll
        for (int c = 0; c < 4; c++) accP[p][c] = 0ULL;   // bits of (0.f, 0.f)

    for (int k0 = 0; k0 < DH; k0 += 32) {
        __syncthreads();
#pragma unroll
        for (int i = tid; i < 32 * DH / 4; i += 256)
            reinterpret_cast<float4*>(Wsh)[i] =
                reinterpret_cast<const float4*>(W + (size_t)k0 * DH)[i];
        // A chunk, transposed store: Ash[kk][node]
#pragma unroll
        for (int i = tid; i < NPB * 8; i += 256) {
            int nl = i >> 3;           // local node 0..63
            int j  = i & 7;            // k sub-chunk of 4
            int n = node0 + nl;
            float4 av = make_float4(0.f, 0.f, 0.f, 0.f);
            if (n < nN)
                av = *reinterpret_cast<const float4*>(&A[(size_t)n * DH + k0 + (j << 2)]);
            Ash[(j * 4 + 0) * AST + nl] = av.x;
            Ash[(j * 4 + 1) * AST + nl] = av.y;
            Ash[(j * 4 + 2) * AST + nl] = av.z;
            Ash[(j * 4 + 3) * AST + nl] = av.w;
        }
        __syncthreads();

#pragma unroll 8
        for (int kk = 0; kk < 32; kk++) {
            float4 w = *reinterpret_cast<const float4*>(&Wsh[kk * DH + lane * 4]);
            unsigned long long wd0 = pk2(w.x, w.x);
            unsigned long long wd1 = pk2(w.y, w.y);
            unsigned long long wd2 = pk2(w.z, w.z);
            unsigned long long wd3 = pk2(w.w, w.w);
            const float* Ar = &Ash[kk * AST + warp * 8];
#pragma unroll
            for (int p = 0; p < 4; p++) {
                unsigned long long pa =
                    *reinterpret_cast<const unsigned long long*>(&Ar[2 * p]);
                accP[p][0] = fma2(pa, wd0, accP[p][0]);
                accP[p][1] = fma2(pa, wd1, accP[p][1]);
                accP[p][2] = fma2(pa, wd2, accP[p][2]);
                accP[p][3] = fma2(pa, wd3, accP[p][3]);
            }
        }
    }

    float4 bb = *reinterpret_cast<const float4*>(&bsh[lane * 4]);
#pragma unroll
    for (int p = 0; p < 4; p++) {
        float a0[4], a1[4];
#pragma unroll
        for (int c = 0; c < 4; c++) upk2(a0[c], a1[c], accP[p][c]);
#pragma unroll
        for (int half = 0; half < 2; half++) {
            int n = node0 + warp * 8 + 2 * p + half;
            if (n >= nN) continue;
            const float* av = half ? a1 : a0;
            float4 o;
            o.x = fmaxf(av[0] + bb.x, 0.f);
            o.y = fmaxf(av[1] + bb.y, 0.f);
            o.z = fmaxf(av[2] + bb.z, 0.f);
            o.w = fmaxf(av[3] + bb.w, 0.f);
            if (mode == 0) {
                float d = g_dis[n];
                __nv_bfloat162 p0 = __float22bfloat162_rn(make_float2(o.x * d, o.y * d));
                __nv_bfloat162 p1 = __float22bfloat162_rn(make_float2(o.z * d, o.w * d));
                uint2 u;
                u.x = *reinterpret_cast<unsigned*>(&p0);
                u.y = *reinterpret_cast<unsigned*>(&p1);
                reinterpret_cast<uint2*>(g_h1b)[(size_t)n * 32 + lane] = u;
            } else {
                int g = __ldg(&gid[n]);
                red_add_v4(reinterpret_cast<float4*>(&g_pooled[(size_t)g * DH]) + lane, o);
                if (lane == 0) atomicAdd(&g_cnt[g], 1.0f);
            }
        }
    }
}

// ---------------- classifier ----------------
__global__ void k_logits(const float* __restrict__ Wc, const float* __restrict__ bc,
                         float* __restrict__ out, int nG) {
    int t = threadIdx.x;      // 512 threads
    int g = t >> 3, c = t & 7;
    if (g >= nG) return;
    float s = 0.f;
#pragma unroll 8
    for (int k = 0; k < DH; k++)
        s = fmaf(g_pooled[g * DH + k], __ldg(&Wc[k * 8 + c]), s);
    float cnt = fmaxf(g_cnt[g], 1.0f);
    out[g * 8 + c] = s / cnt + bc[c];
}

// ---------------- launch ----------------
extern "C" void kernel_launch(void* const* d_in, const int* in_sizes, int n_in,
                              void* d_out, int out_size) {
    const float* x  = (const float*)d_in[0];
    const int*   ei = (const int*)  d_in[1];
    const int*   gid= (const int*)  d_in[2];
    const float* W1 = (const float*)d_in[3];
    const float* b1 = (const float*)d_in[4];
    const float* W2 = (const float*)d_in[5];
    const float* b2 = (const float*)d_in[6];
    const float* Wc = (const float*)d_in[7];
    const float* bc = (const float*)d_in[8];
    float* out = (float*)d_out;

    int nN = in_sizes[0] / DH;
    int nE = in_sizes[1] / 2;
    int nG = out_size / 8;
    const int* src = ei;
    const int* dst = ei + nE;

    const int T = 256;
    int gN   = (nN + T - 1) / T;
    int gN16 = (int)(((long long)nN * 16 + T - 1) / T);
    int gN32 = (int)(((long long)nN * 32 + T - 1) / T);
    int gGemm = (nN + NPB - 1) / NPB;

    k_zero_aux<<<gN, T>>>(nN);

    // histogram + CSR build (vectorized when dst is 16B-aligned, i.e. nE % 4 == 0)
    if ((nE & 3) == 0) {
        int nQ = nE >> 2;
        int gQ = (nQ + T - 1) / T;
        k_hist4<<<gQ, T>>>((const int4*)dst, nQ);
        k_scan<<<1, 1024>>>(nN);
        k_build4<<<gQ, T>>>((const int4*)src, (const int4*)dst, nQ);
    } else {
        int gE4 = (nE / 4 + T) / T;
        k_hist_s<<<gE4, T>>>(dst, nE);
        k_scan<<<1, 1024>>>(nN);
        k_build_s<<<gE4, T>>>(src, dst, nE);
    }

    // pre-scale x into bf16 (+ zero pooled/cnt)
    k_scale_x<<<gN32, T>>>((const float4*)x, nN);

    // layer 1: gather from xb, GEMM -> h1b (bf16, pre-scaled)
    k_gather<<<gN16, T>>>(1, nN);
    k_gemm_relu<<<gGemm, T>>>(W1, b1, gid, nN, 0);

    // layer 2: gather from h1b, GEMM (+fused pooling)
    k_gather<<<gN16, T>>>(0, nN);
    k_gemm_relu<<<gGemm, T>>>(W2, b2, gid, nN, 1);

    // classify
    k_logits<<<1, 512>>>(Wc, bc, out, nG);
}